// round 1
// baseline (speedup 1.0000x reference)
#include <cuda_runtime.h>
#include <cuda_bf16.h>

// Problem constants
#define B    256
#define T    256
#define NQ   1000
#define DK   128
#define DV   128
#define CC   32
#define TOUT 255                 // pred/true length per batch row
#define NROWS (B * TOUT)         // 65280

// ---------------- device scratch (no allocations allowed) ----------------
__device__ float g_wt[NQ * CC];          // softmax(k_emb @ Mk)          [1000,32]
__device__ float g_g [NQ * DK];          // k_emb @ f_W[128:256] + f_b   [1000,128]
__device__ float g_et[2 * NQ * DV];      // sigmoid(v_emb @ e_W + e_b)   [2000,128]
__device__ float g_at[2 * NQ * DV];      // tanh(v_emb @ a_W + a_b)      [2000,128]
__device__ float g_rt[NROWS * DV];       // rt for every (b,t)           [65280,128]

// ---------------- precompute: wt = softmax(k_emb @ Mk) -------------------
// one warp per question row; lane = column c (C == 32)
__global__ void pre_wt_kernel(const float* __restrict__ k_emb,
                              const float* __restrict__ Mk) {
    int warp = threadIdx.x >> 5;
    int lane = threadIdx.x & 31;
    int q = blockIdx.x * 4 + warp;
    if (q >= NQ) return;
    const float* krow = k_emb + q * DK;
    float acc = 0.f;
    #pragma unroll 8
    for (int k = 0; k < DK; k++)
        acc = fmaf(__ldg(krow + k), __ldg(Mk + k * CC + lane), acc);
    // softmax over 32 lanes
    float mx = acc;
    #pragma unroll
    for (int off = 16; off; off >>= 1)
        mx = fmaxf(mx, __shfl_xor_sync(0xffffffffu, mx, off));
    float e = expf(acc - mx);
    float s = e;
    #pragma unroll
    for (int off = 16; off; off >>= 1)
        s += __shfl_xor_sync(0xffffffffu, s, off);
    g_wt[q * CC + lane] = e / s;
}

// ---------------- precompute: g = k_emb @ f_W[128:] + f_b ----------------
__global__ void pre_g_kernel(const float* __restrict__ k_emb,
                             const float* __restrict__ f_W,
                             const float* __restrict__ f_b) {
    __shared__ float sk[DK];
    int q = blockIdx.x;
    int j = threadIdx.x;
    sk[j] = k_emb[q * DK + j];
    __syncthreads();
    float acc = __ldg(f_b + j);
    #pragma unroll 8
    for (int k = 0; k < DK; k++)
        acc = fmaf(sk[k], __ldg(f_W + (DK + k) * DK + j), acc);
    g_g[q * DK + j] = acc;
}

// ---------------- precompute: et/at from v_emb ---------------------------
__global__ void pre_ea_kernel(const float* __restrict__ v_emb,
                              const float* __restrict__ e_W,
                              const float* __restrict__ e_b,
                              const float* __restrict__ a_W,
                              const float* __restrict__ a_b) {
    __shared__ float sv[DV];
    int q = blockIdx.x;          // 0..1999
    int j = threadIdx.x;
    sv[j] = v_emb[q * DV + j];
    __syncthreads();
    float acce = __ldg(e_b + j);
    float acca = __ldg(a_b + j);
    #pragma unroll 8
    for (int k = 0; k < DV; k++) {
        float v = sv[k];
        acce = fmaf(v, __ldg(e_W + k * DV + j), acce);
        acca = fmaf(v, __ldg(a_W + k * DV + j), acca);
    }
    g_et[q * DV + j] = 1.0f / (1.0f + expf(-acce));
    g_at[q * DV + j] = tanhf(acca);
}

// ---------------- sequential scan: register-resident Mvt -----------------
// grid = B blocks, 128 threads. Thread d owns Mvt[:,d] in 32 registers.
// No shared memory, no __syncthreads in the main loop; loads for step t+1
// are prefetched during step t, indices fetched 2 steps ahead.
__global__ void __launch_bounds__(128)
scan_kernel(const int* __restrict__ skills,
            const int* __restrict__ responses,
            const float* __restrict__ Mv0) {
    int b = blockIdx.x;
    int d = threadIdx.x;

    float m[CC];
    #pragma unroll
    for (int c = 0; c < CC; c++) m[c] = __ldg(Mv0 + c * DV + d);

    const int* srow = skills + b * T;
    const int* rrow = responses + b * T;

    // stage: data for t=0
    int st0 = __ldg(srow + 0);
    int q0  = st0 + NQ * __ldg(rrow + 0);
    float4 W[8];
    float e, a;
    {
        const float4* wp = reinterpret_cast<const float4*>(g_wt + st0 * CC);
        #pragma unroll
        for (int u = 0; u < 8; u++) W[u] = __ldg(wp + u);
        e = __ldg(g_et + q0 * DV + d);
        a = __ldg(g_at + q0 * DV + d);
    }
    // indices for t=1
    int st1 = __ldg(srow + 1);
    int q1  = st1 + NQ * __ldg(rrow + 1);

    float* rtp = g_rt + (b * TOUT) * DV + d;

    for (int t = 0; t < TOUT; t++) {
        // prefetch data for t+1
        float4 Wn[8];
        float en = 0.f, an = 0.f;
        if (t < TOUT - 1) {
            const float4* wp = reinterpret_cast<const float4*>(g_wt + st1 * CC);
            #pragma unroll
            for (int u = 0; u < 8; u++) Wn[u] = __ldg(wp + u);
            en = __ldg(g_et + q1 * DV + d);
            an = __ldg(g_at + q1 * DV + d);
        } else {
            #pragma unroll
            for (int u = 0; u < 8; u++) Wn[u] = make_float4(0.f, 0.f, 0.f, 0.f);
        }
        // prefetch indices for t+2
        if (t < TOUT - 2) {
            st1 = __ldg(srow + t + 2);
            q1  = st1 + NQ * __ldg(rrow + t + 2);
        }

        // compute step t: rt[d] = sum_c w[c]*m[c];  m[c] += w[c]*(a - m[c]*e)
        float acc = 0.f;
#define DKVMN_STEP(wv, ci)                         \
        {                                          \
            float w_  = (wv);                      \
            float mo_ = m[ci];                     \
            acc = fmaf(w_, mo_, acc);              \
            float tmp_ = fmaf(mo_, -e, a);         \
            m[ci] = fmaf(w_, tmp_, mo_);           \
        }
#define DKVMN_Q4(u)                                \
        DKVMN_STEP(W[u].x, 4*(u)+0)                \
        DKVMN_STEP(W[u].y, 4*(u)+1)                \
        DKVMN_STEP(W[u].z, 4*(u)+2)                \
        DKVMN_STEP(W[u].w, 4*(u)+3)
        DKVMN_Q4(0) DKVMN_Q4(1) DKVMN_Q4(2) DKVMN_Q4(3)
        DKVMN_Q4(4) DKVMN_Q4(5) DKVMN_Q4(6) DKVMN_Q4(7)
#undef DKVMN_Q4
#undef DKVMN_STEP

        rtp[t * DV] = acc;

        // rotate prefetched data
        #pragma unroll
        for (int u = 0; u < 8; u++) W[u] = Wn[u];
        e = en; a = an;
    }
}

// ---------------- readout GEMM + tanh + dot(p_W) + sigmoid ---------------
// pred[gr] = sigmoid( sum_j p_W[j] * tanh( sum_i rt[gr,i]*f_W[i,j] + g_g[skill,j] ) + p_b )
// 256 threads: j = tid&127, row-half = tid>>7; each thread accumulates 8 rows.
#define GT_ROWS 16
__global__ void __launch_bounds__(256)
readout_kernel(const float* __restrict__ f_W,
               const float* __restrict__ p_W,
               const float* __restrict__ p_b,
               const int* __restrict__ skills,
               const int* __restrict__ responses,
               float* __restrict__ out) {
    __shared__ __align__(16) float xs[GT_ROWS * DK];
    __shared__ float red[GT_ROWS][4];

    int tid  = threadIdx.x;
    int j    = tid & 127;
    int rh   = tid >> 7;          // 0 or 1
    int warp = tid >> 5;          // 0..7
    int wIn  = warp & 3;
    int lane = tid & 31;

    float pwj = __ldg(p_W + j);
    float pb  = __ldg(p_b);

    const int NT = NROWS / GT_ROWS;  // 4080 tiles
    for (int tile = blockIdx.x; tile < NT; tile += gridDim.x) {
        // stage X tile
        const float* xsrc = g_rt + tile * GT_ROWS * DK;
        #pragma unroll
        for (int idx = tid; idx < GT_ROWS * DK; idx += 256) xs[idx] = xsrc[idx];
        __syncthreads();

        float accv[8];
        #pragma unroll
        for (int rr = 0; rr < 8; rr++) {
            int gr = tile * GT_ROWS + rh * 8 + rr;
            int bb = gr / TOUT;
            int tt = gr - bb * TOUT;
            int sk = __ldg(skills + bb * T + tt);
            accv[rr] = __ldg(g_g + sk * DK + j);
        }

        const float* xbase = xs + rh * 8 * DK;
        #pragma unroll 4
        for (int i = 0; i < DK; i += 4) {
            float w0 = __ldg(f_W + (i + 0) * DK + j);
            float w1 = __ldg(f_W + (i + 1) * DK + j);
            float w2 = __ldg(f_W + (i + 2) * DK + j);
            float w3 = __ldg(f_W + (i + 3) * DK + j);
            #pragma unroll
            for (int rr = 0; rr < 8; rr++) {
                float4 xv = *reinterpret_cast<const float4*>(xbase + rr * DK + i);
                accv[rr] = fmaf(xv.x, w0, accv[rr]);
                accv[rr] = fmaf(xv.y, w1, accv[rr]);
                accv[rr] = fmaf(xv.z, w2, accv[rr]);
                accv[rr] = fmaf(xv.w, w3, accv[rr]);
            }
        }

        // tanh -> weighted partial -> warp reduce over j
        #pragma unroll
        for (int rr = 0; rr < 8; rr++) {
            float v = tanhf(accv[rr]) * pwj;
            #pragma unroll
            for (int off = 16; off; off >>= 1)
                v += __shfl_xor_sync(0xffffffffu, v, off);
            if (lane == 0) red[rh * 8 + rr][wIn] = v;
        }
        __syncthreads();
        if (tid < GT_ROWS) {
            float s = red[tid][0] + red[tid][1] + red[tid][2] + red[tid][3] + pb;
            out[tile * GT_ROWS + tid] = 1.0f / (1.0f + expf(-s));
        }
        __syncthreads();
    }
}

// ---------------- true labels -------------------------------------------
__global__ void true_kernel(const int* __restrict__ responses,
                            float* __restrict__ out2) {
    int i = blockIdx.x * blockDim.x + threadIdx.x;
    if (i < NROWS) {
        int b = i / TOUT;
        int t = i - b * TOUT;
        out2[i] = (float)responses[b * T + t + 1];
    }
}

// ---------------- launch -------------------------------------------------
extern "C" void kernel_launch(void* const* d_in, const int* in_sizes, int n_in,
                              void* d_out, int out_size) {
    const int*   skills    = (const int*)  d_in[0];
    const int*   responses = (const int*)  d_in[1];
    const float* k_emb     = (const float*)d_in[2];
    const float* v_emb     = (const float*)d_in[3];
    const float* Mk        = (const float*)d_in[4];
    const float* Mv0       = (const float*)d_in[5];
    const float* f_W       = (const float*)d_in[6];
    const float* f_b       = (const float*)d_in[7];
    const float* p_W       = (const float*)d_in[8];
    const float* p_b       = (const float*)d_in[9];
    const float* e_W       = (const float*)d_in[10];
    const float* e_b       = (const float*)d_in[11];
    const float* a_W       = (const float*)d_in[12];
    const float* a_b       = (const float*)d_in[13];

    float* pred_out = (float*)d_out;
    float* true_out = pred_out + (out_size / 2);   // second half of output

    // precompute gathers (independent, same stream -> ordered before scan)
    pre_wt_kernel<<<250, 128>>>(k_emb, Mk);
    pre_g_kernel <<<NQ, 128>>>(k_emb, f_W, f_b);
    pre_ea_kernel<<<2 * NQ, 128>>>(v_emb, e_W, e_b, a_W, a_b);

    // sequential recurrence -> rt scratch
    scan_kernel<<<B, 128>>>(skills, responses, Mv0);

    // readout GEMM -> pred
    readout_kernel<<<148, 256>>>(f_W, p_W, p_b, skills, responses, pred_out);

    // true labels
    true_kernel<<<(NROWS + 255) / 256, 256>>>(responses, true_out);
}

// round 2
// speedup vs baseline: 1.6893x; 1.6893x over previous
#include <cuda_runtime.h>
#include <cuda_bf16.h>

// Problem constants
#define B    256
#define T    256
#define NQ   1000
#define DK   128
#define DV   128
#define CC   32
#define TOUT 255
#define NROWS (B * TOUT)         // 65280

typedef unsigned long long u64;

// ---------------- packed f32x2 helpers (sm_103a) --------------------------
__device__ __forceinline__ u64 pack2(float lo, float hi) {
    u64 r; asm("mov.b64 %0, {%1, %2};" : "=l"(r) : "f"(lo), "f"(hi)); return r;
}
__device__ __forceinline__ void unpack2(u64 v, float& lo, float& hi) {
    asm("mov.b64 {%0, %1}, %2;" : "=f"(lo), "=f"(hi) : "l"(v));
}
__device__ __forceinline__ u64 fma2(u64 a, u64 b, u64 c) {
    u64 d; asm("fma.rn.f32x2 %0, %1, %2, %3;" : "=l"(d) : "l"(a), "l"(b), "l"(c)); return d;
}

// ---------------- device scratch ------------------------------------------
__device__ __align__(16) float g_wt[NQ * CC];       // softmax(k_emb @ Mk)
__device__ __align__(16) float g_g [NQ * DK];       // k_emb @ f_W[128:] + f_b
__device__ __align__(16) float g_et[2 * NQ * DV];   // sigmoid(v_emb @ e_W + e_b)
__device__ __align__(16) float g_at[2 * NQ * DV];   // tanh(v_emb @ a_W + a_b)
__device__ __align__(16) float g_rt[NROWS * DV];    // rt scratch

// ---------------- precompute: wt = softmax(k_emb @ Mk) --------------------
__global__ void pre_wt_kernel(const float* __restrict__ k_emb,
                              const float* __restrict__ Mk) {
    int warp = threadIdx.x >> 5;
    int lane = threadIdx.x & 31;
    int q = blockIdx.x * 4 + warp;
    if (q >= NQ) return;
    const float* krow = k_emb + q * DK;
    float acc = 0.f;
    #pragma unroll 8
    for (int k = 0; k < DK; k++)
        acc = fmaf(__ldg(krow + k), __ldg(Mk + k * CC + lane), acc);
    float mx = acc;
    #pragma unroll
    for (int off = 16; off; off >>= 1)
        mx = fmaxf(mx, __shfl_xor_sync(0xffffffffu, mx, off));
    float e = expf(acc - mx);
    float s = e;
    #pragma unroll
    for (int off = 16; off; off >>= 1)
        s += __shfl_xor_sync(0xffffffffu, s, off);
    g_wt[q * CC + lane] = e / s;
}

// ---------------- precompute: g = k_emb @ f_W[128:] + f_b -----------------
__global__ void pre_g_kernel(const float* __restrict__ k_emb,
                             const float* __restrict__ f_W,
                             const float* __restrict__ f_b) {
    __shared__ float sk[DK];
    int q = blockIdx.x;
    int j = threadIdx.x;
    sk[j] = k_emb[q * DK + j];
    __syncthreads();
    float acc = __ldg(f_b + j);
    #pragma unroll 8
    for (int k = 0; k < DK; k++)
        acc = fmaf(sk[k], __ldg(f_W + (DK + k) * DK + j), acc);
    g_g[q * DK + j] = acc;
}

// ---------------- precompute: et/at ---------------------------------------
__global__ void pre_ea_kernel(const float* __restrict__ v_emb,
                              const float* __restrict__ e_W,
                              const float* __restrict__ e_b,
                              const float* __restrict__ a_W,
                              const float* __restrict__ a_b) {
    __shared__ float sv[DV];
    int q = blockIdx.x;
    int j = threadIdx.x;
    sv[j] = v_emb[q * DV + j];
    __syncthreads();
    float acce = __ldg(e_b + j);
    float acca = __ldg(a_b + j);
    #pragma unroll 8
    for (int k = 0; k < DV; k++) {
        float v = sv[k];
        acce = fmaf(v, __ldg(e_W + k * DV + j), acce);
        acca = fmaf(v, __ldg(a_W + k * DV + j), acca);
    }
    g_et[q * DV + j] = 1.0f / (1.0f + expf(-acce));
    g_at[q * DV + j] = tanhf(acca);
}

// ---------------- sequential scan ------------------------------------------
// Thread d owns Mvt[:,d] as 16 packed f32x2 registers (pairs over c).
// Ping-pong W buffers via 2x unroll (no register rotation), f32x2 math.

__device__ __forceinline__ void scan_load(const float* __restrict__ wrow,
                                          const float* __restrict__ et,
                                          const float* __restrict__ at,
                                          int s, int q, int d,
                                          u64 W2[16], float& e, float& a) {
    const ulonglong2* wp = reinterpret_cast<const ulonglong2*>(g_wt + s * CC);
    #pragma unroll
    for (int u = 0; u < 8; u++) {
        ulonglong2 v = __ldg(wp + u);
        W2[2 * u]     = v.x;
        W2[2 * u + 1] = v.y;
    }
    e = __ldg(g_et + q * DV + d);
    a = __ldg(g_at + q * DV + d);
    (void)wrow; (void)et; (void)at;
}

__device__ __forceinline__ float scan_step(u64 m2[16], const u64 W2[16],
                                           float e, float a) {
    u64 en2 = pack2(-e, -e);
    u64 a2  = pack2(a, a);
    u64 acc0 = 0ull, acc1 = 0ull;
    #pragma unroll
    for (int p = 0; p < 16; p++) {
        u64 mo = m2[p];
        if (p & 1) acc1 = fma2(W2[p], mo, acc1);
        else       acc0 = fma2(W2[p], mo, acc0);
        u64 tmp = fma2(mo, en2, a2);          // a - e*m
        m2[p] = fma2(W2[p], tmp, mo);         // m + w*(a - e*m)
    }
    float x0, x1, y0, y1;
    unpack2(acc0, x0, x1);
    unpack2(acc1, y0, y1);
    return (x0 + x1) + (y0 + y1);
}

__global__ void __launch_bounds__(128)
scan_kernel(const int* __restrict__ skills,
            const int* __restrict__ responses,
            const float* __restrict__ Mv0) {
    int b = blockIdx.x;
    int d = threadIdx.x;

    u64 m2[16];
    #pragma unroll
    for (int p = 0; p < 16; p++)
        m2[p] = pack2(__ldg(Mv0 + (2 * p) * DV + d),
                      __ldg(Mv0 + (2 * p + 1) * DV + d));

    const int* srow = skills + b * T;
    const int* rrow = responses + b * T;
    float* rtp = g_rt + (b * TOUT) * DV + d;

    // data for step 0
    int sn = __ldg(srow + 0);
    int qn = sn + NQ * __ldg(rrow + 0);
    u64 WA[16]; float eA, aA;
    scan_load(nullptr, nullptr, nullptr, sn, qn, d, WA, eA, aA);
    // indices for step 1
    sn = __ldg(srow + 1);
    qn = sn + NQ * __ldg(rrow + 1);

    for (int t = 0; t < TOUT - 1; t += 2) {
        // load data for step t+1
        u64 WB[16]; float eB, aB;
        scan_load(nullptr, nullptr, nullptr, sn, qn, d, WB, eB, aB);
        // indices for step t+2 (t+2 <= 254 < T, always valid)
        sn = __ldg(srow + t + 2);
        qn = sn + NQ * __ldg(rrow + t + 2);

        rtp[t * DV] = scan_step(m2, WA, eA, aA);

        // load data for step t+2
        scan_load(nullptr, nullptr, nullptr, sn, qn, d, WA, eA, aA);
        // indices for step t+3 (t+3 <= 255 < T, always valid)
        sn = __ldg(srow + t + 3);
        qn = sn + NQ * __ldg(rrow + t + 3);

        rtp[(t + 1) * DV] = scan_step(m2, WB, eB, aB);
    }
    // final step 254 (data already in A)
    rtp[(TOUT - 1) * DV] = scan_step(m2, WA, eA, aA);
}

// ---------------- readout: GEMM + tanh + dot(p_W) + sigmoid ---------------
// Tile: 64 rows x 128 j per block (256 threads).
// Thread (rg = tid>>5, jg = tid&31) computes 8 rows x 4 consecutive j.
// x staged in smem (LDS.64 gives packed i-pairs); f_W via coalesced LDG.128
// (warp covers a full 128-float f_W row). Accumulators packed f32x2 over
// i-parity. Also writes the `true` labels (second output half).
#define RT_ROWS 64
__global__ void __launch_bounds__(256)
readout_kernel(const float* __restrict__ f_W,
               const float* __restrict__ p_W,
               const float* __restrict__ p_b,
               const int* __restrict__ skills,
               const int* __restrict__ responses,
               float* __restrict__ out,
               float* __restrict__ out2) {
    __shared__ __align__(16) float xs[RT_ROWS * DK];

    int tid  = threadIdx.x;
    int jg   = tid & 31;
    int rg   = tid >> 5;          // warp id 0..7
    int j0   = jg * 4;
    int tile = blockIdx.x;
    int row0 = tile * RT_ROWS;

    // stage x tile (64x128 floats, coalesced float4)
    {
        const float4* src = reinterpret_cast<const float4*>(g_rt + row0 * DK);
        float4* dst = reinterpret_cast<float4*>(xs);
        #pragma unroll
        for (int u = 0; u < (RT_ROWS * DK / 4) / 256; u++)
            dst[tid + u * 256] = src[tid + u * 256];
    }

    // init accumulators with g_g gather (packed into even half)
    u64 acc2[8][4];
    #pragma unroll
    for (int r = 0; r < 8; r++) {
        int gr = row0 + rg * 8 + r;
        int bb = gr / TOUT;
        int tt = gr - bb * TOUT;
        int sk = __ldg(skills + bb * T + tt);
        float4 g = __ldg(reinterpret_cast<const float4*>(g_g + sk * DK + j0));
        acc2[r][0] = pack2(g.x, 0.f);
        acc2[r][1] = pack2(g.y, 0.f);
        acc2[r][2] = pack2(g.z, 0.f);
        acc2[r][3] = pack2(g.w, 0.f);
    }
    __syncthreads();

    const float* xb = xs + rg * 8 * DK;

    #pragma unroll 4
    for (int i = 0; i < DK; i += 2) {
        float4 wlo = __ldg(reinterpret_cast<const float4*>(f_W + i * DK + j0));
        float4 whi = __ldg(reinterpret_cast<const float4*>(f_W + (i + 1) * DK + j0));
        u64 w0 = pack2(wlo.x, whi.x);
        u64 w1 = pack2(wlo.y, whi.y);
        u64 w2 = pack2(wlo.z, whi.z);
        u64 w3 = pack2(wlo.w, whi.w);
        #pragma unroll
        for (int r = 0; r < 8; r++) {
            u64 x2 = *reinterpret_cast<const u64*>(xb + r * DK + i);
            acc2[r][0] = fma2(x2, w0, acc2[r][0]);
            acc2[r][1] = fma2(x2, w1, acc2[r][1]);
            acc2[r][2] = fma2(x2, w2, acc2[r][2]);
            acc2[r][3] = fma2(x2, w3, acc2[r][3]);
        }
    }

    // epilogue: tanh, dot p_W, warp-reduce over j (warp == one row group)
    float4 pw = __ldg(reinterpret_cast<const float4*>(p_W + j0));
    float pb  = __ldg(p_b);
    #pragma unroll
    for (int r = 0; r < 8; r++) {
        float l0, h0, l1, h1, l2, h2, l3, h3;
        unpack2(acc2[r][0], l0, h0);
        unpack2(acc2[r][1], l1, h1);
        unpack2(acc2[r][2], l2, h2);
        unpack2(acc2[r][3], l3, h3);
        float s = tanhf(l0 + h0) * pw.x + tanhf(l1 + h1) * pw.y
                + tanhf(l2 + h2) * pw.z + tanhf(l3 + h3) * pw.w;
        #pragma unroll
        for (int off = 16; off; off >>= 1)
            s += __shfl_xor_sync(0xffffffffu, s, off);
        if (jg == 0) {
            int gr = row0 + rg * 8 + r;
            out[gr] = 1.0f / (1.0f + expf(-s));
        }
    }

    // true labels for this tile's rows
    if (tid < RT_ROWS) {
        int gr = row0 + tid;
        int bb = gr / TOUT;
        int tt = gr - bb * TOUT;
        out2[gr] = (float)__ldg(responses + bb * T + tt + 1);
    }
}

// ---------------- launch ----------------------------------------------------
extern "C" void kernel_launch(void* const* d_in, const int* in_sizes, int n_in,
                              void* d_out, int out_size) {
    const int*   skills    = (const int*)  d_in[0];
    const int*   responses = (const int*)  d_in[1];
    const float* k_emb     = (const float*)d_in[2];
    const float* v_emb     = (const float*)d_in[3];
    const float* Mk        = (const float*)d_in[4];
    const float* Mv0       = (const float*)d_in[5];
    const float* f_W       = (const float*)d_in[6];
    const float* f_b       = (const float*)d_in[7];
    const float* p_W       = (const float*)d_in[8];
    const float* p_b       = (const float*)d_in[9];
    const float* e_W       = (const float*)d_in[10];
    const float* e_b       = (const float*)d_in[11];
    const float* a_W       = (const float*)d_in[12];
    const float* a_b       = (const float*)d_in[13];

    float* pred_out = (float*)d_out;
    float* true_out = pred_out + (out_size / 2);

    pre_wt_kernel<<<250, 128>>>(k_emb, Mk);
    pre_g_kernel <<<NQ, 128>>>(k_emb, f_W, f_b);
    pre_ea_kernel<<<2 * NQ, 128>>>(v_emb, e_W, e_b, a_W, a_b);

    scan_kernel<<<B, 128>>>(skills, responses, Mv0);

    readout_kernel<<<NROWS / RT_ROWS, 256>>>(f_W, p_W, p_b, skills, responses,
                                             pred_out, true_out);
}